// round 16
// baseline (speedup 1.0000x reference)
#include <cuda_runtime.h>
#include <math.h>

#define H 1024
#define L 512
#define V 50257

// ---------------- scratch layout (floats) ----------------
#define OFF_ALOG   0        // attn logits (512)
#define OFF_ATT    512      // attn_applied accumulator (1024)  [self-reset]
#define OFF_X      1536     // GRU input x (1024)
#define OFF_GI     2560     // gi (3072)
#define OFF_GH     5632     // gh (3072)
#define OFF_HNEW   8704     // h_new (1024)
#define OFF_LOGITS 9728     // vocab logits (50257)
#define OFF_PART   59985    // MB partial exp-sums
#define OFF_LSE    60429
#define SCRATCH_FLOATS 60432

__device__ float g_scratch[SCRATCH_FLOATS];          // zero-init; ATT self-reset
__device__ int   g_maxbits = 0x80000000;             // self-reset
__device__ int   g_fa, g_fb, g_fc;                   // front barriers (self-reset)
__device__ int   g_c1, g_c2, g_c3;                   // gi / gates / vocab (self-reset)
__device__ int   g_count_ls, g_flag_ls, g_end;       // log-softmax + end (self-reset)

__device__ __forceinline__ int f2ord(float f) {
    int i = __float_as_int(f);
    return (i >= 0) ? i : (i ^ 0x7FFFFFFF);
}
__device__ __forceinline__ float ord2f(int o) {
    return __int_as_float((o >= 0) ? o : (o ^ 0x7FFFFFFF));
}

// cheap spin poll: plain volatile L2 read (no RMW serialization)
__device__ __forceinline__ int vpoll(const int* p) {
    int v;
    asm volatile("ld.volatile.global.s32 %0, [%1];" : "=r"(v) : "l"(p));
    return v;
}
__device__ __forceinline__ void l2_prefetch(const void* p) {
    asm volatile("prefetch.global.L2 [%0];" :: "l"(p));
}

__device__ __forceinline__ float warp_sum(float a) {
    #pragma unroll
    for (int o = 16; o; o >>= 1) a += __shfl_xor_sync(0xFFFFFFFFu, a, o);
    return a;
}

// dot of 8 front-batched float4 (1024 floats) against smem slice
__device__ __forceinline__ float dot8(const float4* __restrict__ wr,
                                      const float4* __restrict__ v4,
                                      int lane) {
    float4 w0 = __ldcs(wr + lane);
    float4 w1 = __ldcs(wr + lane + 32);
    float4 w2 = __ldcs(wr + lane + 64);
    float4 w3 = __ldcs(wr + lane + 96);
    float4 w4 = __ldcs(wr + lane + 128);
    float4 w5 = __ldcs(wr + lane + 160);
    float4 w6 = __ldcs(wr + lane + 192);
    float4 w7 = __ldcs(wr + lane + 224);
    float4 x0 = v4[lane],       x1 = v4[lane + 32];
    float4 x2 = v4[lane + 64],  x3 = v4[lane + 96];
    float4 x4 = v4[lane + 128], x5 = v4[lane + 160];
    float4 x6 = v4[lane + 192], x7 = v4[lane + 224];
    float a = 0.f;
    a += w0.x*x0.x + w0.y*x0.y + w0.z*x0.z + w0.w*x0.w;
    a += w1.x*x1.x + w1.y*x1.y + w1.z*x1.z + w1.w*x1.w;
    a += w2.x*x2.x + w2.y*x2.y + w2.z*x2.z + w2.w*x2.w;
    a += w3.x*x3.x + w3.y*x3.y + w3.z*x3.z + w3.w*x3.w;
    a += w4.x*x4.x + w4.y*x4.y + w4.z*x4.z + w4.w*x4.w;
    a += w5.x*x5.x + w5.y*x5.y + w5.z*x5.z + w5.w*x5.w;
    a += w6.x*x6.x + w6.y*x6.y + w6.z*x6.z + w6.w*x6.w;
    a += w7.x*x7.x + w7.y*x7.y + w7.z*x7.z + w7.w*x7.w;
    return a;
}

// dot of 4 front-batched float4 (512 floats)
__device__ __forceinline__ float dot4(const float4* __restrict__ wr,
                                      const float4* __restrict__ v4,
                                      int lane) {
    float4 w0 = __ldcs(wr + lane);
    float4 w1 = __ldcs(wr + lane + 32);
    float4 w2 = __ldcs(wr + lane + 64);
    float4 w3 = __ldcs(wr + lane + 96);
    float4 x0 = v4[lane],      x1 = v4[lane + 32];
    float4 x2 = v4[lane + 64], x3 = v4[lane + 96];
    float a = 0.f;
    a += w0.x*x0.x + w0.y*x0.y + w0.z*x0.z + w0.w*x0.w;
    a += w1.x*x1.x + w1.y*x1.y + w1.z*x1.z + w1.w*x1.w;
    a += w2.x*x2.x + w2.y*x2.y + w2.z*x2.z + w2.w*x2.w;
    a += w3.x*x3.x + w3.y*x3.y + w3.z*x3.z + w3.w*x3.w;
    return a;
}

// ---------------- the whole decoder in ONE kernel ----------------
// 444 blocks = 148 SMs x 3; __launch_bounds__(256,3): all resident (spin-safe).
#define MB 444
#define MW (MB * 8)    // 3552 warps
__global__ void __launch_bounds__(256, 3)
k_all(const float* __restrict__ attn_W, const float* __restrict__ attn_b,
      const float* __restrict__ W_hh, const float* __restrict__ b_hh,
      const float* __restrict__ comb_W, const float* __restrict__ comb_b,
      const float* __restrict__ W_ih, const float* __restrict__ b_ih,
      const float* __restrict__ out_W, const float* __restrict__ out_b,
      const int* __restrict__ idx, const float* __restrict__ hidden,
      const float* __restrict__ emb, const float* __restrict__ enc,
      float* __restrict__ out_full) {
    __shared__ float sv[2 * H];       // [emb | hidden] -> [emb | att] -> x -> h_new
    __shared__ float spart[8];
    __shared__ float sred[256];
    __shared__ float aw[512];
    __shared__ float smax[8];
    __shared__ float sm[256];
    __shared__ int s_last, s_done;
    int t = threadIdx.x, bid = blockIdx.x;
    int warp = t >> 5, lane = t & 31;

    // load [emb | hidden] in every block
    {
        int row_e = idx[0];
        #pragma unroll
        for (int i = t; i < 512; i += 256) {
            ((float4*)sv)[i] = (i < 256)
                ? ((const float4*)(emb + (size_t)row_e * H))[i]
                : ((const float4*)hidden)[i - 256];
        }
    }
    __syncthreads();

    // ---- P1: attn logits (tasks 0-127) + gh (tasks 128-895), strided ----
    for (int bt = bid; bt < 896; bt += MB) {
        if (bt < 128) {
            int row  = bt * 4 + (warp >> 1);
            int half = warp & 1;
            const float4* wr = (const float4*)(attn_W + (size_t)row * 2 * H + half * H);
            float acc = warp_sum(dot8(wr, (const float4*)(sv + half * H), lane));
            if (lane == 0) spart[warp] = acc;
            __syncthreads();
            if (t < 4) {
                int r = bt * 4 + t;
                g_scratch[OFF_ALOG + r] = spart[2 * t] + spart[2 * t + 1] + attn_b[r];
            }
        } else {
            int row  = (bt - 128) * 4 + (warp >> 1);
            int half = warp & 1;
            const float4* wr = (const float4*)(W_hh + (size_t)row * H + half * 512);
            float acc = warp_sum(dot4(wr, (const float4*)(sv + H + half * 512), lane));
            if (lane == 0) spart[warp] = acc;
            __syncthreads();
            if (t < 4) {
                int r = (bt - 128) * 4 + t;
                g_scratch[OFF_GH + r] = spart[2 * t] + spart[2 * t + 1] + b_hh[r];
            }
        }
        __syncthreads();
    }
    // barrier A (ALOG+GH complete)
    __threadfence();
    if (t == 0) { atomicAdd(&g_fa, 1); while (vpoll(&g_fa) < MB) { } __threadfence(); }
    __syncthreads();

    // ---- P2: apply (blocks 0-63); others prefetch out_W into L2 ----
    if (bid < 64) {
        int bx = bid & 3, by = bid >> 2;
        float v0 = g_scratch[OFF_ALOG + t];
        float v1 = g_scratch[OFF_ALOG + 256 + t];
        sred[t] = fmaxf(v0, v1);
        __syncthreads();
        #pragma unroll
        for (int s = 128; s > 0; s >>= 1) {
            if (t < s) sred[t] = fmaxf(sred[t], sred[t + s]);
            __syncthreads();
        }
        float mx = sred[0];
        __syncthreads();
        float e0 = expf(v0 - mx), e1 = expf(v1 - mx);
        sred[t] = e0 + e1;
        __syncthreads();
        #pragma unroll
        for (int s = 128; s > 0; s >>= 1) {
            if (t < s) sred[t] += sred[t + s];
            __syncthreads();
        }
        float inv = 1.f / sred[0];
        aw[t] = e0 * inv; aw[256 + t] = e1 * inv;
        __syncthreads();
        if (bid == 0) {
            out_full[V + H + t]       = aw[t];
            out_full[V + H + 256 + t] = aw[256 + t];
        }
        int col  = bx * 256 + t;
        int base = by * 32;
        float s = 0.f;
        #pragma unroll
        for (int l = 0; l < 32; l++)
            s += aw[base + l] * __ldcs(enc + (size_t)(base + l) * H + col);
        atomicAdd(&g_scratch[OFF_ATT + col], s);
        __threadfence();
        __syncthreads();
        if (t == 0) atomicAdd(&g_fb, 1);
    }

    // ---- P3: comb (blocks 0-255); blocks 256+ prefetch while waiting ----
    if (bid < 256) {
        if (t == 0) { while (vpoll(&g_fb) < 64) { } __threadfence(); }
        __syncthreads();
        // refresh second half of sv with attn_applied (emb already resident)
        ((float4*)(sv + H))[t] = ((const float4*)(g_scratch + OFF_ATT))[t];
        __syncthreads();
        int row  = bid * 4 + (warp >> 1);
        int half = warp & 1;
        const float4* wr = (const float4*)(comb_W + (size_t)row * 2 * H + half * H);
        float acc = warp_sum(dot8(wr, (const float4*)(sv + half * H), lane));
        if (lane == 0) spart[warp] = acc;
        __syncthreads();
        if (t < 4) {
            int r = bid * 4 + t;
            g_scratch[OFF_X + r] = fmaxf(spart[2 * t] + spart[2 * t + 1] + comb_b[r], 0.f);
        }
        __threadfence();
        __syncthreads();
        if (t == 0) atomicAdd(&g_fc, 1);
    } else {
        // prefetch first ~70 MB of out_W into L2 while comb finishes
        int pid = bid - 256;                       // 0..187
        for (int j = 0; j < 12; j++) {
            if (t == 0) s_done = (vpoll(&g_fc) >= 256);
            __syncthreads();
            if (s_done) break;
            size_t off = ((size_t)(pid + j * 188) * 256 + t) * 32;  // 32 floats = 128 B
            l2_prefetch(out_W + off);
            __syncthreads();
        }
    }
    if (t == 0) { while (vpoll(&g_fc) < 256) { } __threadfence(); }
    __syncthreads();

    // ---- gi: one 1024-col row per warp (rows 0..3071) ----
    ((float4*)sv)[t] = ((const float4*)(g_scratch + OFF_X))[t];
    __syncthreads();
    int gw = bid * 8 + warp;
    if (gw < 3 * H) {
        const float4* wr = (const float4*)(W_ih + (size_t)gw * H);
        float acc = warp_sum(dot8(wr, (const float4*)sv, lane));
        if (lane == 0) g_scratch[OFF_GI + gw] = acc + b_ih[gw];
    }
    __threadfence();
    __syncthreads();
    if (t == 0) atomicAdd(&g_c1, 1);

    // ---- gates (blocks 0-3) ----
    if (bid < 4) {
        if (t == 0) { while (vpoll(&g_c1) < MB) { } __threadfence(); }
        __syncthreads();
        int j = bid * 256 + t;
        float gir = g_scratch[OFF_GI + j],       ghr = g_scratch[OFF_GH + j];
        float giz = g_scratch[OFF_GI + H + j],   ghz = g_scratch[OFF_GH + H + j];
        float gin = g_scratch[OFF_GI + 2*H + j], ghn = g_scratch[OFF_GH + 2*H + j];
        float r = 1.f / (1.f + expf(-(gir + ghr)));
        float z = 1.f / (1.f + expf(-(giz + ghz)));
        float n = tanhf(gin + r * ghn);
        float hn = (1.f - z) * n + z * hidden[j];
        g_scratch[OFF_HNEW + j] = hn;
        out_full[V + j] = hn;                 // second output
        __threadfence();
        __syncthreads();
        if (t == 0) atomicAdd(&g_c2, 1);
    }
    if (t == 0) { while (vpoll(&g_c2) < 4) { } __threadfence(); }
    __syncthreads();

    // ---- vocab logits: register-pipelined prefetch ----
    ((float4*)sv)[t] = ((const float4*)(g_scratch + OFF_HNEW))[t];
    __syncthreads();
    const float4* v4 = (const float4*)sv;
    float m = -INFINITY;
    int row = gw;
    float4 cur[8], nxt[8];
    {
        const float4* wr = (const float4*)(out_W + (size_t)row * H);
        #pragma unroll
        for (int k = 0; k < 8; k++) cur[k] = __ldcs(wr + lane + 32 * k);
    }
    while (row < V) {
        int nrow = row + MW;
        int prow = (nrow < V) ? nrow : 0;
        const float4* wn = (const float4*)(out_W + (size_t)prow * H);
        #pragma unroll
        for (int k = 0; k < 8; k++) nxt[k] = __ldcs(wn + lane + 32 * k);

        float a0 = 0.f, a1 = 0.f, a2 = 0.f, a3 = 0.f;
        #pragma unroll
        for (int k = 0; k < 8; k += 4) {
            float4 x0 = v4[lane + 32 * k],       x1 = v4[lane + 32 * (k + 1)];
            float4 x2 = v4[lane + 32 * (k + 2)], x3 = v4[lane + 32 * (k + 3)];
            a0 += cur[k].x*x0.x + cur[k].y*x0.y + cur[k].z*x0.z + cur[k].w*x0.w;
            a1 += cur[k+1].x*x1.x + cur[k+1].y*x1.y + cur[k+1].z*x1.z + cur[k+1].w*x1.w;
            a2 += cur[k+2].x*x2.x + cur[k+2].y*x2.y + cur[k+2].z*x2.z + cur[k+2].w*x2.w;
            a3 += cur[k+3].x*x3.x + cur[k+3].y*x3.y + cur[k+3].z*x3.z + cur[k+3].w*x3.w;
        }
        float acc = warp_sum((a0 + a1) + (a2 + a3));
        if (lane == 0) {
            float r = acc + out_b[row];
            g_scratch[OFF_LOGITS + row] = r;
            m = fmaxf(m, r);
        }
        #pragma unroll
        for (int k = 0; k < 8; k++) cur[k] = nxt[k];
        row = nrow;
    }
    if (lane == 0) smax[warp] = m;
    __threadfence();
    __syncthreads();
    if (t == 0) {
        float bm = smax[0];
        #pragma unroll
        for (int w = 1; w < 8; w++) bm = fmaxf(bm, smax[w]);
        atomicMax(&g_maxbits, f2ord(bm));
        atomicAdd(&g_c3, 1);
        while (vpoll(&g_c3) < MB) { }
        __threadfence();
    }
    __syncthreads();

    // ---- log-softmax ----
    float gm = ord2f(g_maxbits);
    float s = 0.f;
    for (int i = bid * 256 + t; i < V; i += MB * 256)
        s += expf(g_scratch[OFF_LOGITS + i] - gm);
    sm[t] = s;
    __syncthreads();
    #pragma unroll
    for (int st = 128; st > 0; st >>= 1) {
        if (t < st) sm[t] += sm[t + st];
        __syncthreads();
    }
    if (t == 0) {
        g_scratch[OFF_PART + bid] = sm[0];
        __threadfence();
        int old = atomicAdd(&g_count_ls, 1);
        s_last = (old == MB - 1);
    }
    __syncthreads();
    if (s_last) {
        float p = 0.f;
        for (int i = t; i < MB; i += 256) p += g_scratch[OFF_PART + i];
        sm[t] = p;
        __syncthreads();
        #pragma unroll
        for (int st = 128; st > 0; st >>= 1) {
            if (t < st) sm[t] += sm[t + st];
            __syncthreads();
        }
        if (t == 0) {
            g_scratch[OFF_LSE] = gm + logf(sm[0]);
            __threadfence();
            atomicExch(&g_flag_ls, 1);
        }
    }
    if (t == 0) { while (vpoll(&g_flag_ls) == 0) { } __threadfence(); }
    __syncthreads();
    float lse = g_scratch[OFF_LSE];
    for (int i = bid * 256 + t; i < V; i += MB * 256)
        out_full[i] = g_scratch[OFF_LOGITS + i] - lse;

    // ---- end barrier + self-reset (deterministic across graph replays) ----
    __threadfence();
    __syncthreads();
    if (t == 0) {
        int old = atomicAdd(&g_end, 1);
        if (old == MB - 1) {
            for (int i = 0; i < H; i++) g_scratch[OFF_ATT + i] = 0.f;
            g_maxbits = 0x80000000;
            g_fa = 0; g_fb = 0; g_fc = 0;
            g_c1 = 0; g_c2 = 0; g_c3 = 0;
            g_count_ls = 0; g_flag_ls = 0;
            __threadfence();
            g_end = 0;
        }
    }
}

// ---------------- launch: 1 graph node ----------------
extern "C" void kernel_launch(void* const* d_in, const int* in_sizes, int n_in,
                              void* d_out, int out_size) {
    const int*   input_idx = (const int*)  d_in[0];
    const float* hidden    = (const float*)d_in[1];
    const float* enc       = (const float*)d_in[2];
    const float* emb       = (const float*)d_in[3];
    const float* attn_W    = (const float*)d_in[4];
    const float* attn_b    = (const float*)d_in[5];
    const float* comb_W    = (const float*)d_in[6];
    const float* comb_b    = (const float*)d_in[7];
    const float* W_ih      = (const float*)d_in[8];
    const float* W_hh      = (const float*)d_in[9];
    const float* b_ih      = (const float*)d_in[10];
    const float* b_hh      = (const float*)d_in[11];
    const float* out_W     = (const float*)d_in[12];
    const float* out_b     = (const float*)d_in[13];
    float* out = (float*)d_out;

    k_all<<<MB, 256>>>(attn_W, attn_b, W_hh, b_hh, comb_W, comb_b,
                       W_ih, b_ih, out_W, out_b,
                       input_idx, hidden, emb, enc, out);
}

// round 17
// speedup vs baseline: 1.0745x; 1.0745x over previous
#include <cuda_runtime.h>
#include <math.h>

#define H 1024
#define L 512
#define V 50257

// ---------------- scratch layout (floats) ----------------
#define OFF_ALOG   0        // attn logits (512)
#define OFF_ATT    512      // attn_applied accumulator (1024)
#define OFF_X      1536     // GRU input x (1024)
#define OFF_GI     2560     // gi (3072)
#define OFF_GH     5632     // gh (3072)
#define OFF_HNEW   8704     // h_new (1024)
#define OFF_LOGITS 9728     // vocab logits (50257)
#define OFF_PART   59985    // MB partial exp-sums
#define OFF_LSE    60429
#define SCRATCH_FLOATS 60432

__device__ float g_scratch[SCRATCH_FLOATS];
__device__ int   g_maxbits = 0x80000000;
__device__ int   g_fa, g_fb, g_fe;             // front: attn done / apply done / end
__device__ int   g_c1, g_c2, g_c3;             // mega: gi / gates / vocab
__device__ int   g_count_ls, g_flag_ls;        // mega: log-softmax

__device__ __forceinline__ int f2ord(float f) {
    int i = __float_as_int(f);
    return (i >= 0) ? i : (i ^ 0x7FFFFFFF);
}
__device__ __forceinline__ float ord2f(int o) {
    return __int_as_float((o >= 0) ? o : (o ^ 0x7FFFFFFF));
}

// cheap spin poll: plain volatile L2 read (no RMW serialization)
__device__ __forceinline__ int vpoll(const int* p) {
    int v;
    asm volatile("ld.volatile.global.s32 %0, [%1];" : "=r"(v) : "l"(p));
    return v;
}

__device__ __forceinline__ float warp_sum(float a) {
    #pragma unroll
    for (int o = 16; o; o >>= 1) a += __shfl_xor_sync(0xFFFFFFFFu, a, o);
    return a;
}

// dot of 8 front-batched float4 (1024 floats) against smem slice
__device__ __forceinline__ float dot8(const float4* __restrict__ wr,
                                      const float4* __restrict__ v4,
                                      int lane) {
    float4 w0 = __ldcs(wr + lane);
    float4 w1 = __ldcs(wr + lane + 32);
    float4 w2 = __ldcs(wr + lane + 64);
    float4 w3 = __ldcs(wr + lane + 96);
    float4 w4 = __ldcs(wr + lane + 128);
    float4 w5 = __ldcs(wr + lane + 160);
    float4 w6 = __ldcs(wr + lane + 192);
    float4 w7 = __ldcs(wr + lane + 224);
    float4 x0 = v4[lane],       x1 = v4[lane + 32];
    float4 x2 = v4[lane + 64],  x3 = v4[lane + 96];
    float4 x4 = v4[lane + 128], x5 = v4[lane + 160];
    float4 x6 = v4[lane + 192], x7 = v4[lane + 224];
    float a = 0.f;
    a += w0.x*x0.x + w0.y*x0.y + w0.z*x0.z + w0.w*x0.w;
    a += w1.x*x1.x + w1.y*x1.y + w1.z*x1.z + w1.w*x1.w;
    a += w2.x*x2.x + w2.y*x2.y + w2.z*x2.z + w2.w*x2.w;
    a += w3.x*x3.x + w3.y*x3.y + w3.z*x3.z + w3.w*x3.w;
    a += w4.x*x4.x + w4.y*x4.y + w4.z*x4.z + w4.w*x4.w;
    a += w5.x*x5.x + w5.y*x5.y + w5.z*x5.z + w5.w*x5.w;
    a += w6.x*x6.x + w6.y*x6.y + w6.z*x6.z + w6.w*x6.w;
    a += w7.x*x7.x + w7.y*x7.y + w7.z*x7.z + w7.w*x7.w;
    return a;
}

// dot of 4 front-batched float4 (512 floats)
__device__ __forceinline__ float dot4(const float4* __restrict__ wr,
                                      const float4* __restrict__ v4,
                                      int lane) {
    float4 w0 = __ldcs(wr + lane);
    float4 w1 = __ldcs(wr + lane + 32);
    float4 w2 = __ldcs(wr + lane + 64);
    float4 w3 = __ldcs(wr + lane + 96);
    float4 x0 = v4[lane],      x1 = v4[lane + 32];
    float4 x2 = v4[lane + 64], x3 = v4[lane + 96];
    float a = 0.f;
    a += w0.x*x0.x + w0.y*x0.y + w0.z*x0.z + w0.w*x0.w;
    a += w1.x*x1.x + w1.y*x1.y + w1.z*x1.z + w1.w*x1.w;
    a += w2.x*x2.x + w2.y*x2.y + w2.z*x2.z + w2.w*x2.w;
    a += w3.x*x3.x + w3.y*x3.y + w3.z*x3.z + w3.w*x3.w;
    return a;
}

// ---------------- N1: front — attn (0-127) || gh (128-591), then apply, then comb ----------------
// 592 blocks = 148 x 4, __launch_bounds__(256,4): all resident (spin-safe).
// apply waits ONLY on attn (g_fa==128); comb waits ONLY on apply (g_fb==64);
// gh overlaps apply/comb and just finishes before kernel end.
#define FB 592
__global__ void __launch_bounds__(256, 4)
k_front(const float* __restrict__ attn_W, const float* __restrict__ attn_b,
        const float* __restrict__ W_hh, const float* __restrict__ b_hh,
        const float* __restrict__ comb_W, const float* __restrict__ comb_b,
        const int* __restrict__ idx, const float* __restrict__ hidden,
        const float* __restrict__ emb, const float* __restrict__ enc,
        float* __restrict__ out_full) {
    __shared__ float sv[2 * H];      // [emb | hidden] -> [emb | attn_applied]
    __shared__ float spart[8];
    __shared__ float sred[256];
    __shared__ float aw[512];
    int t = threadIdx.x, bid = blockIdx.x;
    int warp = t >> 5, lane = t & 31;

    // all blocks load [emb | hidden]
    {
        int row_e = idx[0];
        #pragma unroll
        for (int i = t; i < 512; i += 256) {
            ((float4*)sv)[i] = (i < 256)
                ? ((const float4*)(emb + (size_t)row_e * H))[i]
                : ((const float4*)hidden)[i - 256];
        }
    }
    if (bid == 0) {
        #pragma unroll
        for (int i = t; i < H; i += 256) g_scratch[OFF_ATT + i] = 0.f;
        if (t == 0) {
            g_maxbits = 0x80000000;
            g_c1 = 0; g_c2 = 0; g_c3 = 0;
            g_count_ls = 0; g_flag_ls = 0;
        }
    }
    __syncthreads();

    if (bid < 128) {
        // attn: 4 rows x 2 half-row tasks, full 2048 cols via dot8 halves
        int row  = bid * 4 + (warp >> 1);
        int half = warp & 1;
        const float4* wr = (const float4*)(attn_W + (size_t)row * 2 * H + half * H);
        float acc = warp_sum(dot8(wr, (const float4*)(sv + half * H), lane));
        if (lane == 0) spart[warp] = acc;
        __syncthreads();
        if (t < 4) {
            int r = bid * 4 + t;
            g_scratch[OFF_ALOG + r] = spart[2 * t] + spart[2 * t + 1] + attn_b[r];
        }
        __threadfence();
        __syncthreads();
        if (t == 0) atomicAdd(&g_fa, 1);
    } else {
        // gh: tasks 0..767 strided over blocks 128-591 (<=2 tasks each)
        for (int gt = bid - 128; gt < 768; gt += 464) {
            int row  = gt * 4 + (warp >> 1);
            int half = warp & 1;
            const float4* wr = (const float4*)(W_hh + (size_t)row * H + half * 512);
            float acc = warp_sum(dot4(wr, (const float4*)(sv + H + half * 512), lane));
            if (lane == 0) spart[warp] = acc;
            __syncthreads();
            if (t < 4) {
                int r = gt * 4 + t;
                g_scratch[OFF_GH + r] = spart[2 * t] + spart[2 * t + 1] + b_hh[r];
            }
            __syncthreads();
        }
        __threadfence();
    }

    // ---- apply (blocks 0-63): waits only for attn ----
    if (bid < 64) {
        if (t == 0) { while (vpoll(&g_fa) < 128) { } __threadfence(); }
        __syncthreads();
        int bx = bid & 3, by = bid >> 2;
        float v0 = g_scratch[OFF_ALOG + t];
        float v1 = g_scratch[OFF_ALOG + 256 + t];
        sred[t] = fmaxf(v0, v1);
        __syncthreads();
        #pragma unroll
        for (int s = 128; s > 0; s >>= 1) {
            if (t < s) sred[t] = fmaxf(sred[t], sred[t + s]);
            __syncthreads();
        }
        float mx = sred[0];
        __syncthreads();
        float e0 = expf(v0 - mx), e1 = expf(v1 - mx);
        sred[t] = e0 + e1;
        __syncthreads();
        #pragma unroll
        for (int s = 128; s > 0; s >>= 1) {
            if (t < s) sred[t] += sred[t + s];
            __syncthreads();
        }
        float inv = 1.f / sred[0];
        aw[t] = e0 * inv; aw[256 + t] = e1 * inv;
        __syncthreads();
        if (bid == 0) {
            out_full[V + H + t]       = aw[t];
            out_full[V + H + 256 + t] = aw[256 + t];
        }
        int col  = bx * 256 + t;
        int base = by * 32;
        float s = 0.f;
        #pragma unroll
        for (int l = 0; l < 32; l++)
            s += aw[base + l] * __ldcs(enc + (size_t)(base + l) * H + col);
        atomicAdd(&g_scratch[OFF_ATT + col], s);
        __threadfence();
        __syncthreads();
        if (t == 0) atomicAdd(&g_fb, 1);
    }

    // ---- comb (blocks 0-255): waits only for apply ----
    if (bid < 256) {
        if (t == 0) { while (vpoll(&g_fb) < 64) { } __threadfence(); }
        __syncthreads();
        // refresh second half of sv with attn_applied (emb already resident)
        ((float4*)(sv + H))[t] = ((const float4*)(g_scratch + OFF_ATT))[t];
        __syncthreads();
        int row  = bid * 4 + (warp >> 1);
        int half = warp & 1;
        const float4* wr = (const float4*)(comb_W + (size_t)row * 2 * H + half * H);
        float acc = warp_sum(dot8(wr, (const float4*)(sv + half * H), lane));
        if (lane == 0) spart[warp] = acc;
        __syncthreads();
        if (t < 4) {
            int r = bid * 4 + t;
            g_scratch[OFF_X + r] = fmaxf(spart[2 * t] + spart[2 * t + 1] + comb_b[r], 0.f);
        }
        __threadfence();
    }

    // ---- end barrier + self-reset of front counters ----
    __syncthreads();
    if (t == 0) {
        int old = atomicAdd(&g_fe, 1);
        if (old == FB - 1) {
            g_fa = 0; g_fb = 0;
            __threadfence();
            g_fe = 0;
        }
    }
}

// ---------------- N2: mega kernel — gi -> gates -> vocab -> log-softmax ----------------
// (round-14 proven version, verbatim)
#define MB 444
#define MW (MB * 8)    // 3552 warps
__global__ void __launch_bounds__(256, 3)
k_mega(const float* __restrict__ W_ih, const float* __restrict__ b_ih,
       const float* __restrict__ hidden,
       const float* __restrict__ out_W, const float* __restrict__ out_b,
       float* __restrict__ out_full) {
    __shared__ float sbuf[H];
    __shared__ float smax[8];
    __shared__ int s_last;
    int t = threadIdx.x, warp = t >> 5, lane = t & 31;
    int gw = blockIdx.x * 8 + warp;

    // ---- phase 1: gi = x @ W_ih.T + b_ih ----
    ((float4*)sbuf)[t] = ((const float4*)(g_scratch + OFF_X))[t];
    __syncthreads();
    if (gw < 3 * H) {
        const float4* wr = (const float4*)(W_ih + (size_t)gw * H);
        float acc = warp_sum(dot8(wr, (const float4*)sbuf, lane));
        if (lane == 0) g_scratch[OFF_GI + gw] = acc + b_ih[gw];
    }
    __threadfence();
    __syncthreads();
    if (t == 0) atomicAdd(&g_c1, 1);

    // ---- phase 2: GRU gates by blocks 0-3 ----
    if (blockIdx.x < 4) {
        if (t == 0) { while (vpoll(&g_c1) < MB) { } __threadfence(); }
        __syncthreads();
        int j = blockIdx.x * 256 + t;
        float gir = g_scratch[OFF_GI + j],       ghr = g_scratch[OFF_GH + j];
        float giz = g_scratch[OFF_GI + H + j],   ghz = g_scratch[OFF_GH + H + j];
        float gin = g_scratch[OFF_GI + 2*H + j], ghn = g_scratch[OFF_GH + 2*H + j];
        float r = 1.f / (1.f + expf(-(gir + ghr)));
        float z = 1.f / (1.f + expf(-(giz + ghz)));
        float n = tanhf(gin + r * ghn);
        float hn = (1.f - z) * n + z * hidden[j];
        g_scratch[OFF_HNEW + j] = hn;
        out_full[V + j] = hn;                 // second output
        __threadfence();
        __syncthreads();
        if (t == 0) atomicAdd(&g_c2, 1);
    }
    if (t == 0) { while (vpoll(&g_c2) < 4) { } __threadfence(); }
    __syncthreads();

    // ---- phase 3: vocab logits, register-pipelined prefetch ----
    ((float4*)sbuf)[t] = ((const float4*)(g_scratch + OFF_HNEW))[t];
    __syncthreads();
    const float4* v4 = (const float4*)sbuf;
    float m = -INFINITY;
    int row = gw;
    float4 cur[8], nxt[8];
    {
        const float4* wr = (const float4*)(out_W + (size_t)row * H);
        #pragma unroll
        for (int k = 0; k < 8; k++) cur[k] = __ldcs(wr + lane + 32 * k);
    }
    while (row < V) {
        int nrow = row + MW;
        int prow = (nrow < V) ? nrow : 0;
        const float4* wn = (const float4*)(out_W + (size_t)prow * H);
        #pragma unroll
        for (int k = 0; k < 8; k++) nxt[k] = __ldcs(wn + lane + 32 * k);

        float a0 = 0.f, a1 = 0.f, a2 = 0.f, a3 = 0.f;
        #pragma unroll
        for (int k = 0; k < 8; k += 4) {
            float4 x0 = v4[lane + 32 * k],       x1 = v4[lane + 32 * (k + 1)];
            float4 x2 = v4[lane + 32 * (k + 2)], x3 = v4[lane + 32 * (k + 3)];
            a0 += cur[k].x*x0.x + cur[k].y*x0.y + cur[k].z*x0.z + cur[k].w*x0.w;
            a1 += cur[k+1].x*x1.x + cur[k+1].y*x1.y + cur[k+1].z*x1.z + cur[k+1].w*x1.w;
            a2 += cur[k+2].x*x2.x + cur[k+2].y*x2.y + cur[k+2].z*x2.z + cur[k+2].w*x2.w;
            a3 += cur[k+3].x*x3.x + cur[k+3].y*x3.y + cur[k+3].z*x3.z + cur[k+3].w*x3.w;
        }
        float acc = warp_sum((a0 + a1) + (a2 + a3));
        if (lane == 0) {
            float r = acc + out_b[row];
            g_scratch[OFF_LOGITS + row] = r;
            m = fmaxf(m, r);
        }
        #pragma unroll
        for (int k = 0; k < 8; k++) cur[k] = nxt[k];
        row = nrow;
    }
    if (lane == 0) smax[warp] = m;
    __threadfence();
    __syncthreads();
    if (t == 0) {
        float bm = smax[0];
        #pragma unroll
        for (int w = 1; w < 8; w++) bm = fmaxf(bm, smax[w]);
        atomicMax(&g_maxbits, f2ord(bm));
        atomicAdd(&g_c3, 1);
        while (vpoll(&g_c3) < MB) { }
        __threadfence();
    }
    __syncthreads();

    // ---- phase 4: log-softmax ----
    float gm = ord2f(g_maxbits);
    {
        __shared__ float sm[256];
        float s = 0.f;
        for (int i = blockIdx.x * 256 + t; i < V; i += MB * 256)
            s += expf(g_scratch[OFF_LOGITS + i] - gm);
        sm[t] = s;
        __syncthreads();
        #pragma unroll
        for (int st = 128; st > 0; st >>= 1) {
            if (t < st) sm[t] += sm[t + st];
            __syncthreads();
        }
        if (t == 0) {
            g_scratch[OFF_PART + blockIdx.x] = sm[0];
            __threadfence();
            int old = atomicAdd(&g_count_ls, 1);
            s_last = (old == MB - 1);
        }
        __syncthreads();
        if (s_last) {
            float p = 0.f;
            for (int i = t; i < MB; i += 256) p += g_scratch[OFF_PART + i];
            sm[t] = p;
            __syncthreads();
            #pragma unroll
            for (int st = 128; st > 0; st >>= 1) {
                if (t < st) sm[t] += sm[t + st];
                __syncthreads();
            }
            if (t == 0) {
                g_scratch[OFF_LSE] = gm + logf(sm[0]);
                __threadfence();
                atomicExch(&g_flag_ls, 1);
            }
        }
        if (t == 0) { while (vpoll(&g_flag_ls) == 0) { } __threadfence(); }
        __syncthreads();
        float lse = g_scratch[OFF_LSE];
        for (int i = blockIdx.x * 256 + t; i < V; i += MB * 256)
            out_full[i] = g_scratch[OFF_LOGITS + i] - lse;
    }
}

// ---------------- launch: 2 graph nodes ----------------
extern "C" void kernel_launch(void* const* d_in, const int* in_sizes, int n_in,
                              void* d_out, int out_size) {
    const int*   input_idx = (const int*)  d_in[0];
    const float* hidden    = (const float*)d_in[1];
    const float* enc       = (const float*)d_in[2];
    const float* emb       = (const float*)d_in[3];
    const float* attn_W    = (const float*)d_in[4];
    const float* attn_b    = (const float*)d_in[5];
    const float* comb_W    = (const float*)d_in[6];
    const float* comb_b    = (const float*)d_in[7];
    const float* W_ih      = (const float*)d_in[8];
    const float* W_hh      = (const float*)d_in[9];
    const float* b_ih      = (const float*)d_in[10];
    const float* b_hh      = (const float*)d_in[11];
    const float* out_W     = (const float*)d_in[12];
    const float* out_b     = (const float*)d_in[13];
    float* out = (float*)d_out;

    k_front<<<FB, 256>>>(attn_W, attn_b, W_hh, b_hh, comb_W, comb_b,
                         input_idx, hidden, emb, enc, out);
    k_mega <<<MB, 256>>>(W_ih, b_ih, hidden, out_W, out_b, out);
}